// round 13
// baseline (speedup 1.0000x reference)
#include <cuda_runtime.h>
#include <cuda_bf16.h>
#include <math.h>
#include <stdint.h>

// ---------------------------------------------------------------------------
// WindowAttention3D. Main kernel: 512 threads, 1 CTA/SM, W1 resident in smem,
// one-shot 6-head attention, W2 hoisted out of j loop, in-register softmax.
// B=128, T=6, H=W=8 (HW=64), N=384, DIM=192, NH=6, HD=32.
// ---------------------------------------------------------------------------

#define NB    128
#define TT    6
#define HWN   64
#define NTOK  384
#define DIMC  192
#define NHEAD 6
#define HDIM  32

typedef __nv_bfloat16 bf16;

// scratch (device globals). Q/K: [b][h][t][hw][d]; Vt: [b][h][t][d][hw]
__device__ __align__(16) bf16 g_Q [NB * NHEAD * TT * HWN * HDIM];
__device__ __align__(16) bf16 g_K [NB * NHEAD * TT * HWN * HDIM];
__device__ __align__(16) bf16 g_Vt[NB * NHEAD * TT * HWN * HDIM];
__device__ uint32_t g_XPu[TT * NB * 512 * 12];   // XP frags, packed per (i,b,tid512)
__device__ float g_pos[HWN * DIMC];
__device__ __align__(16) bf16 g_x16  [NB * NTOK * DIMC];  // bf16(x)
__device__ __align__(16) bf16 g_xp16 [NB * NTOK * DIMC];  // bf16(x + pos)
// bf16 weights, [n][k] row-major, k-stride 192
__device__ __align__(16) bf16 g_Wqkv[3 * DIMC * DIMC];
__device__ __align__(16) bf16 g_Wo[DIMC * DIMC];
__device__ __align__(16) bf16 g_Wx[DIMC * DIMC];
__device__ __align__(16) bf16 g_W1b[DIMC * DIMC];
__device__ __align__(16) bf16 g_W2b[DIMC * DIMC];

// ---------------------------------------------------------------------------
__device__ __forceinline__ void mma_bf16(float* c, uint32_t a0, uint32_t a1,
                                         uint32_t a2, uint32_t a3,
                                         uint32_t b0, uint32_t b1) {
    asm volatile(
        "mma.sync.aligned.m16n8k16.row.col.f32.bf16.bf16.f32 "
        "{%0,%1,%2,%3}, {%4,%5,%6,%7}, {%8,%9}, {%0,%1,%2,%3};\n"
        : "+f"(c[0]), "+f"(c[1]), "+f"(c[2]), "+f"(c[3])
        : "r"(a0), "r"(a1), "r"(a2), "r"(a3), "r"(b0), "r"(b1));
}

__device__ __forceinline__ void ldsm4(uint32_t* r, uint32_t addr) {
    asm volatile("ldmatrix.sync.aligned.m8n8.x4.shared.b16 {%0,%1,%2,%3}, [%4];"
                 : "=r"(r[0]), "=r"(r[1]), "=r"(r[2]), "=r"(r[3]) : "r"(addr));
}

__device__ __forceinline__ void cp16(uint32_t saddr, const void* gaddr) {
    asm volatile("cp.async.cg.shared.global [%0], [%1], 16;" :: "r"(saddr), "l"(gaddr));
}
__device__ __forceinline__ void cp_commit() { asm volatile("cp.async.commit_group;"); }
template <int N> __device__ __forceinline__ void cp_wait() {
    asm volatile("cp.async.wait_group %0;" :: "n"(N));
}

__device__ __forceinline__ uint32_t s2u(const void* p) {
    return (uint32_t)__cvta_generic_to_shared(p);
}

__device__ __forceinline__ uint32_t packbf(float lo, float hi) {
    uint32_t r;
    asm("cvt.rn.bf16x2.f32 %0, %1, %2;" : "=r"(r) : "f"(hi), "f"(lo));
    return r;
}
__device__ __forceinline__ float2 unpackbf(uint32_t p) {
    __nv_bfloat162 b = *reinterpret_cast<__nv_bfloat162*>(&p);
    return make_float2(__bfloat162float(b.x), __bfloat162float(b.y));
}

// ---------------------------------------------------------------------------
// Kernel 0: weight conversion fp32 -> bf16
// ---------------------------------------------------------------------------
__global__ void prep_kernel(const float* __restrict__ Wqkv, const float* __restrict__ Wproj,
                            const float* __restrict__ W1, const float* __restrict__ W2) {
    int idx = blockIdx.x * 256 + threadIdx.x;
    if (idx < 3 * DIMC * DIMC) g_Wqkv[idx] = __float2bfloat16(Wqkv[idx]);
    if (idx < DIMC * DIMC) {
        int n = idx / DIMC, k = idx % DIMC;
        g_Wo[idx]  = __float2bfloat16(Wproj[n * 384 + k]);
        g_Wx[idx]  = __float2bfloat16(Wproj[n * 384 + 192 + k]);
        g_W1b[idx] = __float2bfloat16(W1[idx]);
        g_W2b[idx] = __float2bfloat16(W2[idx]);
    }
}

// ---------------------------------------------------------------------------
// Kernel 1: sine positional encoding (64 x 192)
// ---------------------------------------------------------------------------
__global__ void pos_kernel() {
    int idx = blockIdx.x * blockDim.x + threadIdx.x;
    if (idx >= HWN * DIMC) return;
    int hw = idx / DIMC, c = idx % DIMC;
    int row = hw >> 3, col = hw & 7;
    const float two_pi = 6.2831853071795864769f;
    const float inv_denom = two_pi / (8.0f + 1e-6f);
    int m;
    float embed;
    if (c < 96) { m = c >> 1;        embed = (float)(row + 1) * inv_denom; }
    else        { m = (c - 96) >> 1; embed = (float)(col + 1) * inv_denom; }
    float freq = powf(10000.0f, (float)m * (1.0f / 48.0f));
    float v = embed / freq;
    g_pos[idx] = (c & 1) ? cosf(v) : sinf(v);
}

// ---------------------------------------------------------------------------
// Kernel 1b: bf16 activation precompute
// ---------------------------------------------------------------------------
__global__ void prep2_kernel(const float* __restrict__ x) {
    int idx = blockIdx.x * 256 + threadIdx.x;
    int base = idx * 8;
    int r = base / DIMC, c = base % DIMC;
    float4 x0 = *(const float4*)(x + base);
    float4 x1 = *(const float4*)(x + base + 4);
    uint4 o;
    o.x = packbf(x0.x, x0.y);
    o.y = packbf(x0.z, x0.w);
    o.z = packbf(x1.x, x1.y);
    o.w = packbf(x1.z, x1.w);
    *(uint4*)(g_x16 + base) = o;
    const float* pp = g_pos + (r & 63) * DIMC + c;
    float4 p0 = *(const float4*)(pp);
    float4 p1 = *(const float4*)(pp + 4);
    uint4 o2;
    o2.x = packbf(x0.x + p0.x, x0.y + p0.y);
    o2.y = packbf(x0.z + p0.z, x0.w + p0.w);
    o2.z = packbf(x1.x + p1.x, x1.y + p1.y);
    o2.w = packbf(x1.z + p1.z, x1.w + p1.w);
    *(uint4*)(g_xp16 + base) = o2;
}

// ---------------------------------------------------------------------------
// 8-warp gemm (qkv kernel, 256 threads): C[2][6][4] += A(64x192, stride 200)
// @ Wbf^T; ping-pong staged, one barrier per 32-k chunk, no trailing barrier.
// ---------------------------------------------------------------------------
__device__ __forceinline__ void gemm8(const bf16* __restrict__ As,
                                      const bf16* __restrict__ Wbf,
                                      bf16* __restrict__ Buf,
                                      float C[2][6][4], int tid) {
    int lane = tid & 31, w = tid >> 5;
    int mr = (w & 1) * 32, nc = (w >> 1) * 48;
    uint32_t bufu = s2u(Buf);
    uint32_t a_off0 = s2u(As) + ((mr + (lane & 15)) * 200 + ((lane >> 4) << 3)) * 2;
    uint32_t a_off1 = a_off0 + 16 * 200 * 2;
    int bn = (lane & 7) + ((lane >> 4) << 3);
    int bk = ((lane >> 3) & 1) << 3;
    int sn = tid >> 2, skq = (tid & 3) * 8;

#pragma unroll
    for (int i2 = 0; i2 < 3; i2++) {
        int n = sn + i2 * 64;
        cp16(bufu + n * 80 + skq * 2, Wbf + n * DIMC + skq);
    }
    cp_commit();

#pragma unroll 1
    for (int c = 0; c < 6; c++) {
        cp_wait<0>();
        __syncthreads();
        if (c < 5) {
            const bf16* Wsrc = Wbf + (c + 1) * 32;
            uint32_t dstb = bufu + ((c + 1) & 1) * 15360;
#pragma unroll
            for (int i2 = 0; i2 < 3; i2++) {
                int n = sn + i2 * 64;
                cp16(dstb + n * 80 + skq * 2, Wsrc + n * DIMC + skq);
            }
            cp_commit();
        }
        uint32_t bb2 = bufu + (c & 1) * 15360;
#pragma unroll
        for (int ks = 0; ks < 2; ks++) {
            int kg = c * 32 + ks * 16;
            uint32_t a0[4], a1[4];
            ldsm4(a0, a_off0 + kg * 2);
            ldsm4(a1, a_off1 + kg * 2);
#pragma unroll
            for (int p = 0; p < 3; p++) {
                uint32_t b[4];
                ldsm4(b, bb2 + ((nc + p * 16 + bn) * 40 + ks * 16 + bk) * 2);
                mma_bf16(C[0][2 * p],     a0[0], a0[1], a0[2], a0[3], b[0], b[1]);
                mma_bf16(C[1][2 * p],     a1[0], a1[1], a1[2], a1[3], b[0], b[1]);
                mma_bf16(C[0][2 * p + 1], a0[0], a0[1], a0[2], a0[3], b[2], b[3]);
                mma_bf16(C[1][2 * p + 1], a1[0], a1[1], a1[2], a1[3], b[2], b[3]);
            }
        }
    }
}

// ---------------------------------------------------------------------------
// 16-warp streamed gemm (main, 512 threads): C[6][4] += A(64x192, stride 200)
// @ Wbf^T. Warp tile 16 rows x 48 cols. One barrier per chunk, no trailing.
// ---------------------------------------------------------------------------
__device__ __forceinline__ void gemm16(const bf16* __restrict__ As,
                                       const bf16* __restrict__ Wbf,
                                       uint32_t bufu,
                                       float C[6][4], int tid) {
    int lane = tid & 31, w = tid >> 5;
    int mr = (w & 3) * 16, nc = (w >> 2) * 48;
    uint32_t a_off = s2u(As) + ((mr + (lane & 15)) * 200 + ((lane >> 4) << 3)) * 2;
    int bn = (lane & 7) + ((lane >> 4) << 3);
    int bk = ((lane >> 3) & 1) << 3;

#pragma unroll
    for (int q = tid; q < 768; q += 512) {
        int n = q >> 2, skq = (q & 3) * 8;
        cp16(bufu + n * 80 + skq * 2, Wbf + n * DIMC + skq);
    }
    cp_commit();

#pragma unroll 1
    for (int c = 0; c < 6; c++) {
        cp_wait<0>();
        __syncthreads();
        if (c < 5) {
            const bf16* Wsrc = Wbf + (c + 1) * 32;
            uint32_t dstb = bufu + ((c + 1) & 1) * 15360;
#pragma unroll
            for (int q = tid; q < 768; q += 512) {
                int n = q >> 2, skq = (q & 3) * 8;
                cp16(dstb + n * 80 + skq * 2, Wsrc + n * DIMC + skq);
            }
            cp_commit();
        }
        uint32_t bb2 = bufu + (c & 1) * 15360;
#pragma unroll
        for (int ks = 0; ks < 2; ks++) {
            int kg = c * 32 + ks * 16;
            uint32_t a[4];
            ldsm4(a, a_off + kg * 2);
#pragma unroll
            for (int p = 0; p < 3; p++) {
                uint32_t b[4];
                ldsm4(b, bb2 + ((nc + p * 16 + bn) * 40 + ks * 16 + bk) * 2);
                mma_bf16(C[2 * p],     a[0], a[1], a[2], a[3], b[0], b[1]);
                mma_bf16(C[2 * p + 1], a[0], a[1], a[2], a[3], b[2], b[3]);
            }
        }
    }
}

// ---------------------------------------------------------------------------
// Resident-weight gemm (main): C[6][4] += A(64x192, stride 200) @ W^T with W
// already in smem at stride 200. NO barriers, NO staging.
// ---------------------------------------------------------------------------
__device__ __forceinline__ void gemm_res(const bf16* __restrict__ As,
                                         uint32_t w1u, float C[6][4], int tid) {
    int lane = tid & 31, w = tid >> 5;
    int mr = (w & 3) * 16, nc = (w >> 2) * 48;
    uint32_t a_off = s2u(As) + ((mr + (lane & 15)) * 200 + ((lane >> 4) << 3)) * 2;
    int bn = (lane & 7) + ((lane >> 4) << 3);
    int bk = ((lane >> 3) & 1) << 3;
#pragma unroll
    for (int ks = 0; ks < 12; ks++) {
        int kg = ks * 16;
        uint32_t a[4];
        ldsm4(a, a_off + kg * 2);
#pragma unroll
        for (int p = 0; p < 3; p++) {
            uint32_t b[4];
            ldsm4(b, w1u + ((nc + p * 16 + bn) * 200 + kg + bk) * 2);
            mma_bf16(C[2 * p],     a[0], a[1], a[2], a[3], b[0], b[1]);
            mma_bf16(C[2 * p + 1], a[0], a[1], a[2], a[3], b[2], b[3]);
        }
    }
}

// ---------------------------------------------------------------------------
// Kernel 2: merged qkv + xp (256 threads). grid (768, 4).
// s=0,1,2 -> Q/K/Vt from g_xp16; s=3 -> XP frags (packed for 512-thread main).
// ---------------------------------------------------------------------------
__global__ __launch_bounds__(256, 2) void qkv_kernel(const float* __restrict__ bproj) {
    extern __shared__ char smc[];
    bf16* As  = (bf16*)smc;
    bf16* Buf = (bf16*)(smc + 25600);

    int tid = threadIdx.x;
    int lane = tid & 31, w = tid >> 5;
    int qr = lane >> 2, qc = lane & 3;
    int cb = blockIdx.x;
    int r0 = cb * 64;
    int s = blockIdx.y;

    {
        const bf16* src = ((s < 3) ? g_xp16 : g_x16) + (size_t)r0 * DIMC;
        uint32_t asu = s2u(As);
#pragma unroll
        for (int it = 0; it < 6; it++) {
            int q = tid + it * 256;
            int r = q / 24, u = q % 24;
            cp16(asu + r * 400 + u * 16, src + r * DIMC + u * 8);
        }
        cp_commit();
    }

    float C[2][6][4];
#pragma unroll
    for (int a = 0; a < 2; a++)
#pragma unroll
        for (int f = 0; f < 6; f++)
#pragma unroll
            for (int u = 0; u < 4; u++) C[a][f][u] = 0.0f;

    const bf16* Wsel = (s < 3) ? (g_Wqkv + (size_t)s * DIMC * DIMC) : g_Wx;
    gemm8(As, Wsel, Buf, C, tid);

    const float SCALE = 0.17677669529663688f;  // 32^-0.5
    int mr = (w & 1) * 32, nc = (w >> 1) * 48;

    if (s < 2) {
        bf16* GD = (s == 0) ? g_Q : g_K;
        float scl = (s == 0) ? SCALE : 1.0f;
#pragma unroll
        for (int mf = 0; mf < 2; mf++)
#pragma unroll
            for (int f = 0; f < 6; f++) {
                int cg = nc + f * 8 + 2 * qc;
                int h = cg >> 5, d = cg & 31;
#pragma unroll
                for (int half = 0; half < 2; half++) {
                    int gr = r0 + mr + mf * 16 + qr + half * 8;
                    int bidx = gr / NTOK, n = gr % NTOK;
                    int t = n >> 6, hw = n & 63;
                    int dst = ((bidx * NHEAD + h) * TT + t) * 2048 + hw * 32 + d;
                    *(uint32_t*)(GD + dst) =
                        packbf(C[mf][f][half * 2 + 0] * scl, C[mf][f][half * 2 + 1] * scl);
                }
            }
    } else if (s == 2) {
#pragma unroll
        for (int mf = 0; mf < 2; mf++)
#pragma unroll
            for (int f = 0; f < 6; f++) {
                int cg = nc + f * 8 + 2 * qc;
                int h = cg >> 5, d = cg & 31;
#pragma unroll
                for (int half = 0; half < 2; half++) {
                    int gr = r0 + mr + mf * 16 + qr + half * 8;
                    int bidx = gr / NTOK, n = gr % NTOK;
                    int t = n >> 6, hw = n & 63;
                    int base = ((bidx * NHEAD + h) * TT + t) * 2048;
                    g_Vt[base + d * 64 + hw]       = __float2bfloat16(C[mf][f][half * 2 + 0]);
                    g_Vt[base + (d + 1) * 64 + hw] = __float2bfloat16(C[mf][f][half * 2 + 1]);
                }
            }
    } else {
        // XP frags packed for main's 512-thread mapping:
        // main: row64 = (w_m&3)*16 + qr + hf*8, col = (w_m>>2)*48 + f*8 + 2qc
        int i2 = cb >> 7, bb2 = cb & 127;
        uint32_t* dstbase = g_XPu + ((size_t)(i2 * NB + bb2) * 512) * 12;
#pragma unroll
        for (int mf = 0; mf < 2; mf++)
#pragma unroll
            for (int f = 0; f < 6; f++) {
                int col = nc + f * 8 + 2 * qc;
                float b0v = __ldg(bproj + col), b1v = __ldg(bproj + col + 1);
#pragma unroll
                for (int half = 0; half < 2; half++) {
                    int row64 = mr + mf * 16 + qr + half * 8;
                    int w_m = (row64 >> 4) + 4 * (w >> 1);
                    int tid_m = w_m * 32 + lane;
                    dstbase[tid_m * 12 + f * 2 + half] =
                        packbf(C[mf][f][half * 2 + 0] + b0v, C[mf][f][half * 2 + 1] + b1v);
                }
            }
    }
}

// ---------------------------------------------------------------------------
// All-heads KV prefetch (512 threads): K 384x40 @kvu, V 192x72 @kvu+30720.
// ---------------------------------------------------------------------------
__device__ __forceinline__ void issue_kv_all(const bf16* __restrict__ Kbase,
                                             const bf16* __restrict__ Vbase,
                                             int j, uint32_t kvu, int tid) {
#pragma unroll
    for (int it = 0; it < 3; it++) {
        int q = tid + it * 512;
        int row = q >> 2, seg = (q & 3) * 8;
        int h = row >> 6, r = row & 63;
        cp16(kvu + (row * 40 + seg) * 2,
             Kbase + (((size_t)h * TT + j) << 11) + r * 32 + seg);
    }
#pragma unroll
    for (int it = 0; it < 3; it++) {
        int q = tid + it * 512;
        int row = q >> 3, seg = (q & 7) * 8;
        int h = row >> 5, d = row & 31;
        cp16(kvu + 30720 + (row * 72 + seg) * 2,
             Vbase + (((size_t)h * TT + j) << 11) + d * 64 + seg);
    }
    cp_commit();
}

// ---------------------------------------------------------------------------
// Kernel 3: per-(i, b), 512 threads, 1 CTA/SM, 211968 B dynamic smem.
// smem: Qall(25600) @0 | Os(25600) @25600 | Ys(25600) @51200 |
//       W1 resident 192x200 bf16 (76800) @76800 |
//       K 384x40 (30720) @153600 (aliased by Wo/W2 stream Buf) |
//       V 192x72 (27648) @184320.
// ---------------------------------------------------------------------------
__global__ __launch_bounds__(512, 1) void main_kernel(
    const float* __restrict__ x, const float* __restrict__ gamma,
    const float* __restrict__ beta, const float* __restrict__ b1,
    const float* __restrict__ b2, float* __restrict__ out) {
    extern __shared__ char smc[];
    bf16* Qall = (bf16*)smc;
    bf16* Os   = (bf16*)(smc + 25600);
    bf16* Ys   = (bf16*)(smc + 51200);
    uint32_t w1u = s2u(smc + 76800);
    uint32_t kvu = s2u(smc + 153600);     // K base; Buf for streamed gemms
    uint32_t vbu = kvu + 30720;           // V base

    int tid = threadIdx.x;
    int lane = tid & 31, w = tid >> 5;
    int qr = lane >> 2, qc = lane & 3;
    int i = blockIdx.x, bb = blockIdx.y;

    int mrG = (w & 3) * 16, ncG = (w >> 2) * 48;   // gemm warp tile
    int bn = (lane & 7) + ((lane >> 4) << 3);
    int bk = ((lane >> 3) & 1) << 3;

    const bf16* Kbase = g_K  + ((size_t)(bb * NHEAD) * TT << 11);
    const bf16* Vbase = g_Vt + ((size_t)(bb * NHEAD) * TT << 11);
    const uint32_t* xpp = g_XPu + ((size_t)(i * NB + bb) * 512 + tid) * 12;

    // stage W1 resident (rows n, k-stride 200)
#pragma unroll
    for (int it = 0; it < 9; it++) {
        int q = tid + it * 512;
        int n = q / 24, kq = (q % 24) * 8;
        cp16(w1u + (n * 200 + kq) * 2, g_W1b + n * DIMC + kq);
    }
    // KV for j=0 and Q (all heads)
    issue_kv_all(Kbase, Vbase, 0, kvu, tid);
    {
        uint32_t qu = s2u(Qall);
#pragma unroll
        for (int it = 0; it < 3; it++) {
            int q = tid + it * 512;
            int h = q >> 8, r = (q & 255) >> 2, seg = (q & 3) * 8;
            cp16(qu + r * 400 + h * 64 + seg * 2,
                 g_Q + ((size_t)((bb * NHEAD + h) * TT + i) << 11) + r * 32 + seg);
        }
        cp_commit();
    }

    float accG[6][4];
#pragma unroll
    for (int f = 0; f < 6; f++)
#pragma unroll
        for (int u = 0; u < 4; u++) accG[f][u] = 0.0f;
    float accs[6][4];

#pragma unroll 1
    for (int j = 0; j < TT; j++) {
        cp_wait<0>();
        __syncthreads();   // KV[j] (+Q,W1 at j=0) visible; prior readers done

        // ---------------- attention: all 6 heads, 24 tasks over 16 warps ----
#pragma unroll 1
        for (int pass = 0; pass < 2; pass++) {
            int t = w + pass * 16;
            if (t < 24) {
                int h = t >> 2, rg = t & 3;
                int mrS = rg * 16;

                float Sc[8][4];
#pragma unroll
                for (int f = 0; f < 8; f++)
#pragma unroll
                    for (int u = 0; u < 4; u++) Sc[f][u] = 0.0f;
                {
                    uint32_t qbase = s2u(Qall) +
                        ((mrS + (lane & 15)) * 200 + h * 32 + ((lane >> 4) << 3)) * 2;
#pragma unroll
                    for (int ks = 0; ks < 2; ks++) {
                        uint32_t a[4];
                        ldsm4(a, qbase + ks * 32);
#pragma unroll
                        for (int p2 = 0; p2 < 4; p2++) {
                            uint32_t bfr[4];
                            ldsm4(bfr, kvu + ((h * 64 + p2 * 16 + bn) * 40 + ks * 16 + bk) * 2);
                            mma_bf16(Sc[2 * p2],     a[0], a[1], a[2], a[3], bfr[0], bfr[1]);
                            mma_bf16(Sc[2 * p2 + 1], a[0], a[1], a[2], a[3], bfr[2], bfr[3]);
                        }
                    }
                }

                // in-warp softmax over full 64-col rows
#pragma unroll
                for (int r2 = 0; r2 < 2; r2++) {
                    float m = -1e30f;
#pragma unroll
                    for (int f = 0; f < 8; f++)
                        m = fmaxf(m, fmaxf(Sc[f][2 * r2], Sc[f][2 * r2 + 1]));
                    m = fmaxf(m, __shfl_xor_sync(0xffffffffu, m, 1));
                    m = fmaxf(m, __shfl_xor_sync(0xffffffffu, m, 2));
                    float s = 0.0f;
#pragma unroll
                    for (int f = 0; f < 8; f++) {
                        Sc[f][2 * r2]     = __expf(Sc[f][2 * r2] - m);
                        Sc[f][2 * r2 + 1] = __expf(Sc[f][2 * r2 + 1] - m);
                        s += Sc[f][2 * r2] + Sc[f][2 * r2 + 1];
                    }
                    s += __shfl_xor_sync(0xffffffffu, s, 1);
                    s += __shfl_xor_sync(0xffffffffu, s, 2);
                    float inv = 1.0f / s;
#pragma unroll
                    for (int f = 0; f < 8; f++) {
                        Sc[f][2 * r2]     *= inv;
                        Sc[f][2 * r2 + 1] *= inv;
                    }
                }

                // O = P @ V^T (16 rows x 32 d); V is [h*32+d][hw] stride 72
                float Oc[4][4];
#pragma unroll
                for (int f = 0; f < 4; f++)
#pragma unroll
                    for (int u = 0; u < 4; u++) Oc[f][u] = 0.0f;
#pragma unroll
                for (int ks = 0; ks < 4; ks++) {
                    uint32_t a0 = packbf(Sc[2 * ks][0],     Sc[2 * ks][1]);
                    uint32_t a1 = packbf(Sc[2 * ks][2],     Sc[2 * ks][3]);
                    uint32_t a2 = packbf(Sc[2 * ks + 1][0], Sc[2 * ks + 1][1]);
                    uint32_t a3 = packbf(Sc[2 * ks + 1][2], Sc[2 * ks + 1][3]);
#pragma unroll
                    for (int p2 = 0; p2 < 2; p2++) {
                        uint32_t bfr[4];
                        ldsm4(bfr, vbu + ((h * 32 + p2 * 16 + bn) * 72 + ks * 16 + bk) * 2);
                        mma_bf16(Oc[2 * p2],     a0, a1, a2, a3, bfr[0], bfr[1]);
                        mma_bf16(Oc[2 * p2 + 1], a0, a1, a2, a3, bfr[2], bfr[3]);
                    }
                }
#pragma unroll
                for (int f = 0; f < 4; f++) {
                    int col = h * 32 + f * 8 + 2 * qc;
                    *(uint32_t*)(Os + (mrS + qr) * 200 + col)     = packbf(Oc[f][0], Oc[f][1]);
                    *(uint32_t*)(Os + (mrS + qr + 8) * 200 + col) = packbf(Oc[f][2], Oc[f][3]);
                }
            }
        }
        // no explicit barrier: Wo gemm16's c=0 barrier orders Os writes

        // ---------------- y = Os @ Wo^T + XP (streamed via Buf=K region) ----
#pragma unroll
        for (int f = 0; f < 6; f++)
#pragma unroll
            for (int u = 0; u < 4; u++) accs[f][u] = 0.0f;
        gemm16(Os, g_Wo, kvu, accs, tid);
        {
            uint32_t xpr[12];
#pragma unroll
            for (int u = 0; u < 3; u++)
                *(uint4*)(xpr + u * 4) = *(const uint4*)(xpp + u * 4);
#pragma unroll
            for (int f = 0; f < 6; f++) {
                int col = ncG + f * 8 + 2 * qc;
#pragma unroll
                for (int hf = 0; hf < 2; hf++) {
                    int row = mrG + qr + hf * 8;
                    float2 xv = unpackbf(xpr[f * 2 + hf]);
                    *(uint32_t*)(Ys + row * 200 + col) =
                        packbf(accs[f][hf * 2 + 0] + xv.x, accs[f][hf * 2 + 1] + xv.y);
                }
            }
        }
        __syncthreads();   // Ys writes visible; also Wo Buf reads all done

        // ---------------- LayerNorm rows of Ys (4 rows per warp) ----------
#pragma unroll
        for (int rr = 0; rr < 4; rr++) {
            int row = w * 4 + rr;
            float2 vv[3];
            float s1 = 0.0f, s2 = 0.0f;
#pragma unroll
            for (int u = 0; u < 3; u++) {
                vv[u] = unpackbf(*(const uint32_t*)(Ys + row * 200 + 2 * lane + 64 * u));
                s1 += vv[u].x + vv[u].y;
                s2 += vv[u].x * vv[u].x + vv[u].y * vv[u].y;
            }
#pragma unroll
            for (int off = 16; off; off >>= 1) {
                s1 += __shfl_xor_sync(0xffffffffu, s1, off);
                s2 += __shfl_xor_sync(0xffffffffu, s2, off);
            }
            float mu = s1 * (1.0f / 192.0f);
            float var = s2 * (1.0f / 192.0f) - mu * mu;
            float rstd = rsqrtf(var + 1e-5f);
#pragma unroll
            for (int u = 0; u < 3; u++) {
                int c = 2 * lane + 64 * u;
                float y0 = (vv[u].x - mu) * rstd * __ldg(gamma + c)     + __ldg(beta + c);
                float y1 = (vv[u].y - mu) * rstd * __ldg(gamma + c + 1) + __ldg(beta + c + 1);
                *(uint32_t*)(Ys + row * 200 + c) = packbf(y0, y1);
            }
        }
        __syncthreads();   // LN'd Ys visible before resident W1 gemm ldsm

        // ---------------- accG += gelu(Ys @ W1^T + b1)  (resident, 0 bar) --
#pragma unroll
        for (int f = 0; f < 6; f++)
#pragma unroll
            for (int u = 0; u < 4; u++) accs[f][u] = 0.0f;
        gemm_res(Ys, w1u, accs, tid);
#pragma unroll
        for (int f = 0; f < 6; f++) {
            int col = ncG + f * 8 + 2 * qc;
            float b0v = __ldg(b1 + col), b1v = __ldg(b1 + col + 1);
#pragma unroll
            for (int hf = 0; hf < 2; hf++) {
                float h0 = accs[f][hf * 2 + 0] + b0v;
                float h1 = accs[f][hf * 2 + 1] + b1v;
                accG[f][hf * 2 + 0] += 0.5f * h0 * (1.0f + erff(h0 * 0.70710678118654752f));
                accG[f][hf * 2 + 1] += 0.5f * h1 * (1.0f + erff(h1 * 0.70710678118654752f));
            }
        }

        // prefetch next-j KV: K region (=Wo Buf) free since the Ys barrier;
        // V region untouched by gemms. W1 gemm doesn't use KV.
        if (j < 5)
            issue_kv_all(Kbase, Vbase, j + 1, kvu, tid);
    }

    // ---------------- single W2 GEMM on the j-summed gelu tile --------------
#pragma unroll
    for (int f = 0; f < 6; f++) {
        int col = ncG + f * 8 + 2 * qc;
#pragma unroll
        for (int hf = 0; hf < 2; hf++) {
            int row = mrG + qr + hf * 8;
            *(uint32_t*)(Os + row * 200 + col) =
                packbf(accG[f][hf * 2 + 0], accG[f][hf * 2 + 1]);
        }
    }
#pragma unroll
    for (int f = 0; f < 6; f++)
#pragma unroll
        for (int u = 0; u < 4; u++) accs[f][u] = 0.0f;
    gemm16(Os, g_W2b, kvu, accs, tid);   // c=0 barrier orders Os writes

    // ---------------- write out: [x | x + acc/T + b2] ----------------------
#pragma unroll
    for (int f = 0; f < 6; f++) {
        int col = ncG + f * 8 + 2 * qc;
        float b20 = __ldg(b2 + col), b21 = __ldg(b2 + col + 1);
#pragma unroll
        for (int hf = 0; hf < 2; hf++) {
            int row = mrG + qr + hf * 8;
            int n = i * 64 + row;
            size_t base = (size_t)bb * NTOK + n;
            float2 xv = *(const float2*)(x + base * DIMC + col);
            *(float2*)(out + base * (2 * DIMC) + col) = xv;
            float2 ov;
            ov.x = xv.x + accs[f][hf * 2 + 0] * (1.0f / 6.0f) + b20;
            ov.y = xv.y + accs[f][hf * 2 + 1] * (1.0f / 6.0f) + b21;
            *(float2*)(out + base * (2 * DIMC) + DIMC + col) = ov;
        }
    }
}

// ---------------------------------------------------------------------------
extern "C" void kernel_launch(void* const* d_in, const int* in_sizes, int n_in,
                              void* d_out, int out_size) {
    (void)in_sizes; (void)n_in; (void)out_size;
    const float* x     = (const float*)d_in[0];
    const float* Wqkv  = (const float*)d_in[1];
    const float* Wproj = (const float*)d_in[2];
    const float* bproj = (const float*)d_in[3];
    const float* gamma = (const float*)d_in[4];
    const float* beta  = (const float*)d_in[5];
    const float* W1    = (const float*)d_in[6];
    const float* b1    = (const float*)d_in[7];
    const float* W2    = (const float*)d_in[8];
    const float* b2    = (const float*)d_in[9];
    float* out = (float*)d_out;

    pos_kernel<<<48, 256>>>();
    prep_kernel<<<432, 256>>>(Wqkv, Wproj, W1, W2);
    prep2_kernel<<<4608, 256>>>(x);

    const int gsmem = 25600 + 30720;  // 56320 B
    cudaFuncSetAttribute(qkv_kernel, cudaFuncAttributeMaxDynamicSharedMemorySize, gsmem);
    qkv_kernel<<<dim3(768, 4), 256, gsmem>>>(bproj);

    const int main_smem = 211968;
    cudaFuncSetAttribute(main_kernel, cudaFuncAttributeMaxDynamicSharedMemorySize, main_smem);
    main_kernel<<<dim3(TT, NB), 512, main_smem>>>(x, gamma, beta, b1, b2, out);
}

// round 15
// speedup vs baseline: 1.1175x; 1.1175x over previous
#include <cuda_runtime.h>
#include <cuda_bf16.h>
#include <math.h>
#include <stdint.h>

// ---------------------------------------------------------------------------
// WindowAttention3D: bf16 mma + ldmatrix + cp.async; single-sync gemm
// pipeline, bf16 precomputed activations, merged QKV (one CTA, A staged once),
// in-register softmax, W2 GEMM hoisted out of the j loop.
// B=128, T=6, H=W=8 (HW=64), N=384, DIM=192, NH=6, HD=32.
// ---------------------------------------------------------------------------

#define NB    128
#define TT    6
#define HWN   64
#define NTOK  384
#define DIMC  192
#define NHEAD 6
#define HDIM  32

typedef __nv_bfloat16 bf16;

// scratch (device globals). Q/K: [b][h][t][hw][d]; Vt: [b][h][t][d][hw]
__device__ __align__(16) bf16 g_Q [NB * NHEAD * TT * HWN * HDIM];
__device__ __align__(16) bf16 g_K [NB * NHEAD * TT * HWN * HDIM];
__device__ __align__(16) bf16 g_Vt[NB * NHEAD * TT * HWN * HDIM];
__device__ uint32_t g_XPu[TT * NB * 256 * 24];   // XP frags, packed per (i,b,tid)
__device__ float g_pos[HWN * DIMC];
__device__ __align__(16) bf16 g_x16  [NB * NTOK * DIMC];  // bf16(x)
__device__ __align__(16) bf16 g_xp16 [NB * NTOK * DIMC];  // bf16(x + pos)
// bf16 weights, [n][k] row-major, k-stride 192
__device__ __align__(16) bf16 g_Wqkv[3 * DIMC * DIMC];
__device__ __align__(16) bf16 g_Wo[DIMC * DIMC];
__device__ __align__(16) bf16 g_Wx[DIMC * DIMC];
__device__ __align__(16) bf16 g_W1b[DIMC * DIMC];
__device__ __align__(16) bf16 g_W2b[DIMC * DIMC];

// ---------------------------------------------------------------------------
__device__ __forceinline__ void mma_bf16(float* c, uint32_t a0, uint32_t a1,
                                         uint32_t a2, uint32_t a3,
                                         uint32_t b0, uint32_t b1) {
    asm volatile(
        "mma.sync.aligned.m16n8k16.row.col.f32.bf16.bf16.f32 "
        "{%0,%1,%2,%3}, {%4,%5,%6,%7}, {%8,%9}, {%0,%1,%2,%3};\n"
        : "+f"(c[0]), "+f"(c[1]), "+f"(c[2]), "+f"(c[3])
        : "r"(a0), "r"(a1), "r"(a2), "r"(a3), "r"(b0), "r"(b1));
}

__device__ __forceinline__ void ldsm4(uint32_t* r, uint32_t addr) {
    asm volatile("ldmatrix.sync.aligned.m8n8.x4.shared.b16 {%0,%1,%2,%3}, [%4];"
                 : "=r"(r[0]), "=r"(r[1]), "=r"(r[2]), "=r"(r[3]) : "r"(addr));
}

__device__ __forceinline__ void cp16(uint32_t saddr, const void* gaddr) {
    asm volatile("cp.async.cg.shared.global [%0], [%1], 16;" :: "r"(saddr), "l"(gaddr));
}
__device__ __forceinline__ void cp_commit() { asm volatile("cp.async.commit_group;"); }
template <int N> __device__ __forceinline__ void cp_wait() {
    asm volatile("cp.async.wait_group %0;" :: "n"(N));
}

__device__ __forceinline__ uint32_t s2u(const void* p) {
    return (uint32_t)__cvta_generic_to_shared(p);
}

__device__ __forceinline__ uint32_t packbf(float lo, float hi) {
    uint32_t r;
    asm("cvt.rn.bf16x2.f32 %0, %1, %2;" : "=r"(r) : "f"(hi), "f"(lo));
    return r;
}
__device__ __forceinline__ float2 unpackbf(uint32_t p) {
    __nv_bfloat162 b = *reinterpret_cast<__nv_bfloat162*>(&p);
    return make_float2(__bfloat162float(b.x), __bfloat162float(b.y));
}

// ---------------------------------------------------------------------------
// Kernel 0: weight conversion fp32 -> bf16
// ---------------------------------------------------------------------------
__global__ void prep_kernel(const float* __restrict__ Wqkv, const float* __restrict__ Wproj,
                            const float* __restrict__ W1, const float* __restrict__ W2) {
    int idx = blockIdx.x * 256 + threadIdx.x;
    if (idx < 3 * DIMC * DIMC) g_Wqkv[idx] = __float2bfloat16(Wqkv[idx]);
    if (idx < DIMC * DIMC) {
        int n = idx / DIMC, k = idx % DIMC;
        g_Wo[idx]  = __float2bfloat16(Wproj[n * 384 + k]);
        g_Wx[idx]  = __float2bfloat16(Wproj[n * 384 + 192 + k]);
        g_W1b[idx] = __float2bfloat16(W1[idx]);
        g_W2b[idx] = __float2bfloat16(W2[idx]);
    }
}

// ---------------------------------------------------------------------------
// Kernel 1: sine positional encoding (64 x 192)
// ---------------------------------------------------------------------------
__global__ void pos_kernel() {
    int idx = blockIdx.x * blockDim.x + threadIdx.x;
    if (idx >= HWN * DIMC) return;
    int hw = idx / DIMC, c = idx % DIMC;
    int row = hw >> 3, col = hw & 7;
    const float two_pi = 6.2831853071795864769f;
    const float inv_denom = two_pi / (8.0f + 1e-6f);
    int m;
    float embed;
    if (c < 96) { m = c >> 1;        embed = (float)(row + 1) * inv_denom; }
    else        { m = (c - 96) >> 1; embed = (float)(col + 1) * inv_denom; }
    float freq = powf(10000.0f, (float)m * (1.0f / 48.0f));
    float v = embed / freq;
    g_pos[idx] = (c & 1) ? cosf(v) : sinf(v);
}

// ---------------------------------------------------------------------------
// Kernel 1b: bf16 activation precompute
// ---------------------------------------------------------------------------
__global__ void prep2_kernel(const float* __restrict__ x) {
    int idx = blockIdx.x * 256 + threadIdx.x;
    int base = idx * 8;
    int r = base / DIMC, c = base % DIMC;
    float4 x0 = *(const float4*)(x + base);
    float4 x1 = *(const float4*)(x + base + 4);
    uint4 o;
    o.x = packbf(x0.x, x0.y);
    o.y = packbf(x0.z, x0.w);
    o.z = packbf(x1.x, x1.y);
    o.w = packbf(x1.z, x1.w);
    *(uint4*)(g_x16 + base) = o;
    const float* pp = g_pos + (r & 63) * DIMC + c;
    float4 p0 = *(const float4*)(pp);
    float4 p1 = *(const float4*)(pp + 4);
    uint4 o2;
    o2.x = packbf(x0.x + p0.x, x0.y + p0.y);
    o2.y = packbf(x0.z + p0.z, x0.w + p0.w);
    o2.z = packbf(x1.x + p1.x, x1.y + p1.y);
    o2.w = packbf(x1.z + p1.z, x1.w + p1.w);
    *(uint4*)(g_xp16 + base) = o2;
}

// ---------------------------------------------------------------------------
// bf16 warp-mma GEMM, single-sync pipeline: C[2][6][4] += A(64x192, stride 200)
// @ Wbf^T. One barrier per 32-k chunk; no trailing barrier (see NOTE).
// ---------------------------------------------------------------------------
__device__ __forceinline__ void gemm_bf16(const bf16* __restrict__ As,
                                          const bf16* __restrict__ Wbf,
                                          bf16* __restrict__ Buf,
                                          float C[2][6][4], int tid) {
    int lane = tid & 31, w = tid >> 5;
    int mr = (w & 1) * 32, nc = (w >> 1) * 48;
    uint32_t bufu = s2u(Buf);
    uint32_t a_off0 = s2u(As) + ((mr + (lane & 15)) * 200 + ((lane >> 4) << 3)) * 2;
    uint32_t a_off1 = a_off0 + 16 * 200 * 2;
    int bn = (lane & 7) + ((lane >> 4) << 3);
    int bk = ((lane >> 3) & 1) << 3;
    int sn = tid >> 2, skq = (tid & 3) * 8;

#pragma unroll
    for (int i2 = 0; i2 < 3; i2++) {
        int n = sn + i2 * 64;
        cp16(bufu + n * 80 + skq * 2, Wbf + n * DIMC + skq);
    }
    cp_commit();

#pragma unroll 1
    for (int c = 0; c < 6; c++) {
        cp_wait<0>();
        __syncthreads();
        if (c < 5) {
            const bf16* Wsrc = Wbf + (c + 1) * 32;
            uint32_t dstb = bufu + ((c + 1) & 1) * 15360;
#pragma unroll
            for (int i2 = 0; i2 < 3; i2++) {
                int n = sn + i2 * 64;
                cp16(dstb + n * 80 + skq * 2, Wsrc + n * DIMC + skq);
            }
            cp_commit();
        }
        uint32_t bb2 = bufu + (c & 1) * 15360;
#pragma unroll
        for (int ks = 0; ks < 2; ks++) {
            int kg = c * 32 + ks * 16;
            uint32_t a0[4], a1[4];
            ldsm4(a0, a_off0 + kg * 2);
            ldsm4(a1, a_off1 + kg * 2);
#pragma unroll
            for (int p = 0; p < 3; p++) {
                uint32_t b[4];
                ldsm4(b, bb2 + ((nc + p * 16 + bn) * 40 + ks * 16 + bk) * 2);
                mma_bf16(C[0][2 * p],     a0[0], a0[1], a0[2], a0[3], b[0], b[1]);
                mma_bf16(C[1][2 * p],     a1[0], a1[1], a1[2], a1[3], b[0], b[1]);
                mma_bf16(C[0][2 * p + 1], a0[0], a0[1], a0[2], a0[3], b[2], b[3]);
                mma_bf16(C[1][2 * p + 1], a1[0], a1[1], a1[2], a1[3], b[2], b[3]);
            }
        }
    }
    // NOTE: no trailing barrier. Callers must not overwrite Buf or A without a
    // barrier (next gemm's internal c=0 barrier, or an explicit one). Buffer-0
    // restaging by a subsequent gemm is safe: the c=5 top barrier retired all
    // buffer-0 readers (c=4) before any warp can return and restage it.
    // A last-chunk mma may still be in flight on other warps at return.
}

// ---------------------------------------------------------------------------
// Kernel 2: merged qkv + xp. grid (768, 2):
//   s=0: one CTA stages A (g_xp16 tile) ONCE, runs Q,K,V gemms sequentially.
//   s=1: XP frags from g_x16 @ Wx.
// smem: As(25600) + Buf(30720).
// ---------------------------------------------------------------------------
__global__ __launch_bounds__(256, 2) void qkv_kernel(const float* __restrict__ bproj) {
    extern __shared__ char smc[];
    bf16* As  = (bf16*)smc;
    bf16* Buf = (bf16*)(smc + 25600);

    int tid = threadIdx.x;
    int lane = tid & 31, w = tid >> 5;
    int qr = lane >> 2, qc = lane & 3;
    int cb = blockIdx.x;
    int r0 = cb * 64;
    int sgrp = blockIdx.y;

    {
        const bf16* src = ((sgrp == 0) ? g_xp16 : g_x16) + (size_t)r0 * DIMC;
        uint32_t asu = s2u(As);
#pragma unroll
        for (int it = 0; it < 6; it++) {
            int q = tid + it * 256;
            int r = q / 24, u = q % 24;
            cp16(asu + r * 400 + u * 16, src + r * DIMC + u * 8);
        }
        cp_commit();
    }

    const float SCALE = 0.17677669529663688f;  // 32^-0.5
    int mr = (w & 1) * 32, nc = (w >> 1) * 48;

    float C[2][6][4];

    if (sgrp == 0) {
        // ---- three gemms sharing the staged A tile ----
#pragma unroll 1
        for (int s = 0; s < 3; s++) {
#pragma unroll
            for (int a = 0; a < 2; a++)
#pragma unroll
                for (int f = 0; f < 6; f++)
#pragma unroll
                    for (int u = 0; u < 4; u++) C[a][f][u] = 0.0f;
            gemm_bf16(As, g_Wqkv + (size_t)s * DIMC * DIMC, Buf, C, tid);

            if (s < 2) {
                bf16* GD = (s == 0) ? g_Q : g_K;
                float scl = (s == 0) ? SCALE : 1.0f;
#pragma unroll
                for (int mf = 0; mf < 2; mf++)
#pragma unroll
                    for (int f = 0; f < 6; f++) {
                        int cg = nc + f * 8 + 2 * qc;
                        int h = cg >> 5, d = cg & 31;
#pragma unroll
                        for (int half = 0; half < 2; half++) {
                            int gr = r0 + mr + mf * 16 + qr + half * 8;
                            int bidx = gr / NTOK, n = gr % NTOK;
                            int t = n >> 6, hw = n & 63;
                            int dst = ((bidx * NHEAD + h) * TT + t) * 2048 + hw * 32 + d;
                            *(uint32_t*)(GD + dst) =
                                packbf(C[mf][f][half * 2 + 0] * scl,
                                       C[mf][f][half * 2 + 1] * scl);
                        }
                    }
            } else {
                // V transposed: [b][h][t][d][hw]
#pragma unroll
                for (int mf = 0; mf < 2; mf++)
#pragma unroll
                    for (int f = 0; f < 6; f++) {
                        int cg = nc + f * 8 + 2 * qc;
                        int h = cg >> 5, d = cg & 31;
#pragma unroll
                        for (int half = 0; half < 2; half++) {
                            int gr = r0 + mr + mf * 16 + qr + half * 8;
                            int bidx = gr / NTOK, n = gr % NTOK;
                            int t = n >> 6, hw = n & 63;
                            int base = ((bidx * NHEAD + h) * TT + t) * 2048;
                            g_Vt[base + d * 64 + hw] =
                                __float2bfloat16(C[mf][f][half * 2 + 0]);
                            g_Vt[base + (d + 1) * 64 + hw] =
                                __float2bfloat16(C[mf][f][half * 2 + 1]);
                        }
                    }
            }
        }
    } else {
        // ---- XP fragments: chunk cb maps to (i = cb>>7, bb = cb&127) ----
#pragma unroll
        for (int a = 0; a < 2; a++)
#pragma unroll
            for (int f = 0; f < 6; f++)
#pragma unroll
                for (int u = 0; u < 4; u++) C[a][f][u] = 0.0f;
        gemm_bf16(As, g_Wx, Buf, C, tid);

        int i = cb >> 7, bb = cb & 127;
        uint32_t* dst = g_XPu + ((size_t)(i * NB + bb) * 256 + tid) * 24;
#pragma unroll
        for (int mf = 0; mf < 2; mf++)
#pragma unroll
            for (int f = 0; f < 6; f++) {
                int col = nc + f * 8 + 2 * qc;
                float b0v = __ldg(bproj + col), b1v = __ldg(bproj + col + 1);
#pragma unroll
                for (int hf = 0; hf < 2; hf++)
                    dst[(mf * 6 + f) * 2 + hf] =
                        packbf(C[mf][f][hf * 2 + 0] + b0v, C[mf][f][hf * 2 + 1] + b1v);
            }
    }
}

// ---------------------------------------------------------------------------
// Head-pair K/V prefetch into a KV buffer: K 128x40 @+0, V 64x72 @+10240.
// ---------------------------------------------------------------------------
__device__ __forceinline__ void issue_pair(const bf16* __restrict__ Kbase,
                                           const bf16* __restrict__ Vbase,
                                           int j, int pp, uint32_t kvb, int tid) {
#pragma unroll
    for (int it = 0; it < 2; it++) {
        int q = tid + it * 256;
        int row = q >> 2, seg = (q & 3) * 8;
        int h = 2 * pp + (row >> 6), r = row & 63;
        cp16(kvb + (row * 40 + seg) * 2,
             Kbase + (((size_t)h * TT + j) << 11) + r * 32 + seg);
    }
#pragma unroll
    for (int it = 0; it < 2; it++) {
        int q = tid + it * 256;
        int row = q >> 3, seg = (q & 7) * 8;
        int h = 2 * pp + (row >> 5), d = row & 31;
        cp16(kvb + 10240 + (row * 72 + seg) * 2,
             Vbase + (((size_t)h * TT + j) << 11) + d * 64 + seg);
    }
    cp_commit();
}

// ---------------------------------------------------------------------------
// Kernel 3: per-(i, b) fused attention + proj + LN + MLP(W1) + register
// accumulation of gelu over j; W2 GEMM hoisted to the end (linearity).
// grid (6, 128), 256 threads, 107520 B dynamic smem -> 2 CTAs/SM.
// ---------------------------------------------------------------------------
__global__ __launch_bounds__(256, 2) void main_kernel(
    const float* __restrict__ x, const float* __restrict__ gamma,
    const float* __restrict__ beta, const float* __restrict__ b1,
    const float* __restrict__ b2, float* __restrict__ out) {
    extern __shared__ char smc[];
    bf16* Qall = (bf16*)smc;
    bf16* Os   = (bf16*)(smc + 25600);
    bf16* Ys   = (bf16*)(smc + 51200);
    bf16* Buf  = (bf16*)(smc + 76800);
    uint32_t kvu = s2u(smc + 51200);

    int tid = threadIdx.x;
    int lane = tid & 31, w = tid >> 5;
    int qr = lane >> 2, qc = lane & 3;
    int i = blockIdx.x, bb = blockIdx.y;

    int mrG = (w & 1) * 32, ncG = (w >> 1) * 48;   // gemm warp tile
    int g = w >> 2, wl = w & 3;                     // attention: head group, warp
    int mrS = wl * 16;
    int bn = (lane & 7) + ((lane >> 4) << 3);
    int bk = ((lane >> 3) & 1) << 3;

    const bf16* Kbase = g_K  + ((size_t)(bb * NHEAD) * TT << 11);
    const bf16* Vbase = g_Vt + ((size_t)(bb * NHEAD) * TT << 11);
    const uint32_t* xpp = g_XPu + ((size_t)(i * NB + bb) * 256 + tid) * 24;

    issue_pair(Kbase, Vbase, 0, 0, kvu, tid);

    // stage Q (all 6 heads, this i) into Qall[hw][h*32+d]
    {
        uint32_t qu = s2u(Qall);
#pragma unroll
        for (int it = 0; it < 6; it++) {
            int q = tid + it * 256;
            int h = q >> 8, r = (q & 255) >> 2, seg = (q & 3) * 8;
            cp16(qu + r * 400 + h * 64 + seg * 2,
                 g_Q + ((size_t)((bb * NHEAD + h) * TT + i) << 11) + r * 32 + seg);
        }
        cp_commit();
    }

    float accG[2][6][4];   // fp32 sum of gelu outputs over j (thread-local coords)
#pragma unroll
    for (int a = 0; a < 2; a++)
#pragma unroll
        for (int f = 0; f < 6; f++)
#pragma unroll
            for (int u = 0; u < 4; u++) accG[a][f][u] = 0.0f;
    float accs[2][6][4];

#pragma unroll 1
    for (int j = 0; j < TT; j++) {
        // ---------------- attention: 3 head-pairs ----------------
#pragma unroll 1
        for (int pp = 0; pp < 3; pp++) {
            int b = (j + pp) & 1;
            cp_wait<0>();
            __syncthreads();   // KV[b] (+Q at j=0) visible; KV[b^1] readers done
            if (pp < 2)
                issue_pair(Kbase, Vbase, j, pp + 1, kvu + ((j + pp + 1) & 1) * 19456, tid);

            int h = 2 * pp + g;
            uint32_t kb = kvu + b * 19456;
            uint32_t vb = kb + 10240;

            // S = Q @ K^T : warp = 16 rows x 64 cols
            float Sc[8][4];
#pragma unroll
            for (int f = 0; f < 8; f++)
#pragma unroll
                for (int u = 0; u < 4; u++) Sc[f][u] = 0.0f;
            {
                uint32_t qbase = s2u(Qall) +
                    ((mrS + (lane & 15)) * 200 + h * 32 + ((lane >> 4) << 3)) * 2;
#pragma unroll
                for (int ks = 0; ks < 2; ks++) {
                    uint32_t a[4];
                    ldsm4(a, qbase + ks * 32);
#pragma unroll
                    for (int p2 = 0; p2 < 4; p2++) {
                        uint32_t bf[4];
                        ldsm4(bf, kb + ((g * 64 + p2 * 16 + bn) * 40 + ks * 16 + bk) * 2);
                        mma_bf16(Sc[2 * p2],     a[0], a[1], a[2], a[3], bf[0], bf[1]);
                        mma_bf16(Sc[2 * p2 + 1], a[0], a[1], a[2], a[3], bf[2], bf[3]);
                    }
                }
            }

            // in-warp softmax over full 64-col rows
#pragma unroll
            for (int r2 = 0; r2 < 2; r2++) {
                float m = -1e30f;
#pragma unroll
                for (int f = 0; f < 8; f++)
                    m = fmaxf(m, fmaxf(Sc[f][2 * r2], Sc[f][2 * r2 + 1]));
                m = fmaxf(m, __shfl_xor_sync(0xffffffffu, m, 1));
                m = fmaxf(m, __shfl_xor_sync(0xffffffffu, m, 2));
                float s = 0.0f;
#pragma unroll
                for (int f = 0; f < 8; f++) {
                    Sc[f][2 * r2]     = __expf(Sc[f][2 * r2] - m);
                    Sc[f][2 * r2 + 1] = __expf(Sc[f][2 * r2 + 1] - m);
                    s += Sc[f][2 * r2] + Sc[f][2 * r2 + 1];
                }
                s += __shfl_xor_sync(0xffffffffu, s, 1);
                s += __shfl_xor_sync(0xffffffffu, s, 2);
                float inv = 1.0f / s;
#pragma unroll
                for (int f = 0; f < 8; f++) {
                    Sc[f][2 * r2]     *= inv;
                    Sc[f][2 * r2 + 1] *= inv;
                }
            }

            // O = P @ V^T : P stays in registers as A-frags
            {
                float Oc[4][4];
#pragma unroll
                for (int f = 0; f < 4; f++)
#pragma unroll
                    for (int u = 0; u < 4; u++) Oc[f][u] = 0.0f;
#pragma unroll
                for (int ks = 0; ks < 4; ks++) {
                    uint32_t a0 = packbf(Sc[2 * ks][0],     Sc[2 * ks][1]);
                    uint32_t a1 = packbf(Sc[2 * ks][2],     Sc[2 * ks][3]);
                    uint32_t a2 = packbf(Sc[2 * ks + 1][0], Sc[2 * ks + 1][1]);
                    uint32_t a3 = packbf(Sc[2 * ks + 1][2], Sc[2 * ks + 1][3]);
#pragma unroll
                    for (int p2 = 0; p2 < 2; p2++) {
                        uint32_t bf[4];
                        ldsm4(bf, vb + ((g * 32 + p2 * 16 + bn) * 72 + ks * 16 + bk) * 2);
                        mma_bf16(Oc[2 * p2],     a0, a1, a2, a3, bf[0], bf[1]);
                        mma_bf16(Oc[2 * p2 + 1], a0, a1, a2, a3, bf[2], bf[3]);
                    }
                }
#pragma unroll
                for (int f = 0; f < 4; f++) {
                    int col = h * 32 + f * 8 + 2 * qc;
                    *(uint32_t*)(Os + (mrS + qr) * 200 + col)     = packbf(Oc[f][0], Oc[f][1]);
                    *(uint32_t*)(Os + (mrS + qr + 8) * 200 + col) = packbf(Oc[f][2], Oc[f][3]);
                }
            }
        }
        __syncthreads();   // Os complete; KV reads done before Wo staging aliases

        // ---------------- y = Os @ Wo^T + XP ----------------
#pragma unroll
        for (int a = 0; a < 2; a++)
#pragma unroll
            for (int f = 0; f < 6; f++)
#pragma unroll
                for (int u = 0; u < 4; u++) accs[a][f][u] = 0.0f;
        gemm_bf16(Os, g_Wo, Buf, accs, tid);
        {
            uint32_t xpr[24];
#pragma unroll
            for (int u = 0; u < 6; u++)
                *(uint4*)(xpr + u * 4) = *(const uint4*)(xpp + u * 4);
#pragma unroll
            for (int mf = 0; mf < 2; mf++)
#pragma unroll
                for (int f = 0; f < 6; f++) {
                    int col = ncG + f * 8 + 2 * qc;
#pragma unroll
                    for (int hf = 0; hf < 2; hf++) {
                        int row = mrG + mf * 16 + qr + hf * 8;
                        float2 xv = unpackbf(xpr[(mf * 6 + f) * 2 + hf]);
                        *(uint32_t*)(Ys + row * 200 + col) =
                            packbf(accs[mf][f][hf * 2 + 0] + xv.x,
                                   accs[mf][f][hf * 2 + 1] + xv.y);
                    }
                }
        }
        __syncthreads();   // all Ys writes visible before LN row reads

        // ---------------- LayerNorm rows of Ys ----------------
#pragma unroll
        for (int rr = 0; rr < 8; rr++) {
            int row = w * 8 + rr;
            float2 vv[3];
            float s1 = 0.0f, s2 = 0.0f;
#pragma unroll
            for (int u = 0; u < 3; u++) {
                vv[u] = unpackbf(*(const uint32_t*)(Ys + row * 200 + 2 * lane + 64 * u));
                s1 += vv[u].x + vv[u].y;
                s2 += vv[u].x * vv[u].x + vv[u].y * vv[u].y;
            }
#pragma unroll
            for (int off = 16; off; off >>= 1) {
                s1 += __shfl_xor_sync(0xffffffffu, s1, off);
                s2 += __shfl_xor_sync(0xffffffffu, s2, off);
            }
            float mu = s1 * (1.0f / 192.0f);
            float var = s2 * (1.0f / 192.0f) - mu * mu;
            float rstd = rsqrtf(var + 1e-5f);
#pragma unroll
            for (int u = 0; u < 3; u++) {
                int c = 2 * lane + 64 * u;
                float y0 = (vv[u].x - mu) * rstd * __ldg(gamma + c)     + __ldg(beta + c);
                float y1 = (vv[u].y - mu) * rstd * __ldg(gamma + c + 1) + __ldg(beta + c + 1);
                *(uint32_t*)(Ys + row * 200 + c) = packbf(y0, y1);
            }
        }
        // no barrier: W1 gemm's internal c=0 barrier orders LN writes vs ldsm

        // ---------------- accG += gelu(Ys @ W1^T + b1)  (registers only) ----
#pragma unroll
        for (int a = 0; a < 2; a++)
#pragma unroll
            for (int f = 0; f < 6; f++)
#pragma unroll
                for (int u = 0; u < 4; u++) accs[a][f][u] = 0.0f;
        gemm_bf16(Ys, g_W1b, Buf, accs, tid);
#pragma unroll
        for (int mf = 0; mf < 2; mf++)
#pragma unroll
            for (int f = 0; f < 6; f++) {
                int col = ncG + f * 8 + 2 * qc;
                float b0v = __ldg(b1 + col), b1v = __ldg(b1 + col + 1);
#pragma unroll
                for (int hf = 0; hf < 2; hf++) {
                    float h0 = accs[mf][f][hf * 2 + 0] + b0v;
                    float h1 = accs[mf][f][hf * 2 + 1] + b1v;
                    accG[mf][f][hf * 2 + 0] +=
                        0.5f * h0 * (1.0f + erff(h0 * 0.70710678118654752f));
                    accG[mf][f][hf * 2 + 1] +=
                        0.5f * h1 * (1.0f + erff(h1 * 0.70710678118654752f));
                }
            }

        // barrier before KV prefetch: Ys/Buf readers (W1 gemm) must be done
        // before cp.async overwrites the aliased KV region.
        __syncthreads();
        if (j < 5)
            issue_pair(Kbase, Vbase, j + 1, 0, kvu + ((j + 1) & 1) * 19456, tid);
    }

    // ---------------- single W2 GEMM on the j-summed gelu tile ----------------
#pragma unroll
    for (int mf = 0; mf < 2; mf++)
#pragma unroll
        for (int f = 0; f < 6; f++) {
            int col = ncG + f * 8 + 2 * qc;
#pragma unroll
            for (int hf = 0; hf < 2; hf++) {
                int row = mrG + mf * 16 + qr + hf * 8;
                *(uint32_t*)(Os + row * 200 + col) =
                    packbf(accG[mf][f][hf * 2 + 0], accG[mf][f][hf * 2 + 1]);
            }
        }
#pragma unroll
    for (int a = 0; a < 2; a++)
#pragma unroll
        for (int f = 0; f < 6; f++)
#pragma unroll
            for (int u = 0; u < 4; u++) accs[a][f][u] = 0.0f;
    gemm_bf16(Os, g_W2b, Buf, accs, tid);   // c=0 barrier orders Os writes

    // ---------------- write out: [x | x + acc/T + b2] ----------------
#pragma unroll
    for (int mf = 0; mf < 2; mf++)
#pragma unroll
        for (int f = 0; f < 6; f++) {
            int col = ncG + f * 8 + 2 * qc;
            float b20 = __ldg(b2 + col), b21 = __ldg(b2 + col + 1);
#pragma unroll
            for (int hf = 0; hf < 2; hf++) {
                int row = mrG + mf * 16 + qr + hf * 8;
                int n = i * 64 + row;
                size_t base = (size_t)bb * NTOK + n;
                float2 xv = *(const float2*)(x + base * DIMC + col);
                *(float2*)(out + base * (2 * DIMC) + col) = xv;
                float2 ov;
                ov.x = xv.x + accs[mf][f][hf * 2 + 0] * (1.0f / 6.0f) + b20;
                ov.y = xv.y + accs[mf][f][hf * 2 + 1] * (1.0f / 6.0f) + b21;
                *(float2*)(out + base * (2 * DIMC) + DIMC + col) = ov;
            }
        }
}

// ---------------------------------------------------------------------------
extern "C" void kernel_launch(void* const* d_in, const int* in_sizes, int n_in,
                              void* d_out, int out_size) {
    (void)in_sizes; (void)n_in; (void)out_size;
    const float* x     = (const float*)d_in[0];
    const float* Wqkv  = (const float*)d_in[1];
    const float* Wproj = (const float*)d_in[2];
    const float* bproj = (const float*)d_in[3];
    const float* gamma = (const float*)d_in[4];
    const float* beta  = (const float*)d_in[5];
    const float* W1    = (const float*)d_in[6];
    const float* b1    = (const float*)d_in[7];
    const float* W2    = (const float*)d_in[8];
    const float* b2    = (const float*)d_in[9];
    float* out = (float*)d_out;

    pos_kernel<<<48, 256>>>();
    prep_kernel<<<432, 256>>>(Wqkv, Wproj, W1, W2);
    prep2_kernel<<<4608, 256>>>(x);

    const int gsmem = 25600 + 30720;  // 56320 B
    cudaFuncSetAttribute(qkv_kernel, cudaFuncAttributeMaxDynamicSharedMemorySize, gsmem);
    qkv_kernel<<<dim3(768, 2), 256, gsmem>>>(bproj);

    const int main_smem = 107520;
    cudaFuncSetAttribute(main_kernel, cudaFuncAttributeMaxDynamicSharedMemorySize, main_smem);
    main_kernel<<<dim3(TT, NB), 256, main_smem>>>(x, gamma, beta, b1, b2, out);
}